// round 11
// baseline (speedup 1.0000x reference)
#include <cuda_runtime.h>

// LIF neuron forward: T=8 leaky-integrate-fire scan.
// 128 MiB read + 128 MiB write per launch.
//
// R8 (second unchanged resubmit after two consecutive infra failures):
// 256-bit global accesses (ld/st.global.v8.b32, sm_100a). All prior levers
// (MLP, occupancy, store batching, L2 pinning at frac 1.0 & 0.65) proved
// neutral at ~5.75 TB/s. Transaction width is the last structural lever:
// half the request count, longer DRAM bursts per request. Interleaved
// per-timestep (R1 proved == batched) to keep regs low.

constexpr int T_STEPS = 8;

__device__ __forceinline__ void ldg256(const unsigned* p, unsigned v[8]) {
    asm volatile("ld.global.nc.v8.b32 {%0,%1,%2,%3,%4,%5,%6,%7}, [%8];"
                 : "=r"(v[0]), "=r"(v[1]), "=r"(v[2]), "=r"(v[3]),
                   "=r"(v[4]), "=r"(v[5]), "=r"(v[6]), "=r"(v[7])
                 : "l"(p));
}

__device__ __forceinline__ void stg256(unsigned* p, const unsigned v[8]) {
    asm volatile("st.global.cs.v8.b32 [%0], {%1,%2,%3,%4,%5,%6,%7,%8};"
                 :: "l"(p),
                    "r"(v[0]), "r"(v[1]), "r"(v[2]), "r"(v[3]),
                    "r"(v[4]), "r"(v[5]), "r"(v[6]), "r"(v[7])
                 : "memory");
}

__global__ __launch_bounds__(256) void lif_kernel(
    const unsigned* __restrict__ x,
    unsigned* __restrict__ out,
    int n8)               // 8-float groups per timestep
{
    int i = blockIdx.x * blockDim.x + threadIdx.x;
    if (i >= n8) return;

    float mem[8] = {0.f, 0.f, 0.f, 0.f, 0.f, 0.f, 0.f, 0.f};

#pragma unroll
    for (int t = 0; t < T_STEPS; t++) {
        unsigned v[8];
        ldg256(&x[((size_t)t * n8 + i) * 8], v);

#pragma unroll
        for (int k = 0; k < 8; k++) {
            float m = 0.5f * (mem[k] + __uint_as_float(v[k]));
            bool fire = m > 0.5f;
            mem[k] = fire ? 0.0f : m;
            v[k] = fire ? 0x3f800000u : 0u;   // 1.0f : 0.0f
        }

        stg256(&out[((size_t)t * n8 + i) * 8], v);
    }
}

extern "C" void kernel_launch(void* const* d_in, const int* in_sizes, int n_in,
                              void* d_out, int out_size)
{
    const unsigned* x = (const unsigned*)d_in[0];
    unsigned* out = (unsigned*)d_out;

    int total = in_sizes[0];            // 33,554,432
    int per_t = total / T_STEPS;        // 4,194,304
    int n8 = per_t / 8;                 // 524,288 float8 groups per timestep

    int threads = 256;
    int blocks = (n8 + threads - 1) / threads;   // 2048

    lif_kernel<<<blocks, threads>>>(x, out, n8);
}

// round 12
// speedup vs baseline: 1.0250x; 1.0250x over previous
#include <cuda_runtime.h>

// LIF neuron forward: T=8 leaky-integrate-fire scan.
// 128 MiB read + 128 MiB write per launch.
//
// FINAL (R7 config, re-verified): this workload is memory-roofline-bound at
// ~5.7-5.9 TB/s sustained mixed R/W on this part. Falsified levers: MLP
// depth, occupancy, store batching, L2 residency pinning (frac 1.0 & 0.65),
// 256-bit transactions (regression). Best measured wall: 45.088 us.
//   - loads:  createpolicy.fractional.L2::evict_last 0.65 -> ld cache_hint
//   - stores: st.global.cs
//   - phase-separated read burst -> register recurrence -> write burst

constexpr int T_STEPS = 8;

__device__ __forceinline__ float4 ldg_hint(const float4* p, unsigned long long pol) {
    float4 v;
    asm volatile("ld.global.nc.L2::cache_hint.v4.f32 {%0,%1,%2,%3}, [%4], %5;"
                 : "=f"(v.x), "=f"(v.y), "=f"(v.z), "=f"(v.w)
                 : "l"(p), "l"(pol));
    return v;
}

__device__ __forceinline__ void stg_evict_first(float4* p, float4 v) {
    asm volatile("st.global.cs.v4.f32 [%0], {%1,%2,%3,%4};"
                 :: "l"(p), "f"(v.x), "f"(v.y), "f"(v.z), "f"(v.w)
                 : "memory");
}

__global__ __launch_bounds__(256, 4) void lif_kernel(
    const float4* __restrict__ x,
    float4* __restrict__ out,
    int n4)               // float4 elements per timestep
{
    int i = blockIdx.x * blockDim.x + threadIdx.x;
    if (i >= n4) return;

    unsigned long long pol;
    asm volatile("createpolicy.fractional.L2::evict_last.b64 %0, 0.65;" : "=l"(pol));

    // Phase 1: all 8 strided loads back-to-back (one read burst).
    float4 xv[T_STEPS];
#pragma unroll
    for (int t = 0; t < T_STEPS; t++) {
        xv[t] = ldg_hint(&x[(size_t)t * n4 + i], pol);
    }

    // Phase 2: recurrence entirely in registers; spike overwrites xv[t].
    float4 mem = make_float4(0.f, 0.f, 0.f, 0.f);
#pragma unroll
    for (int t = 0; t < T_STEPS; t++) {
        float sx, sy, sz, sw;

        mem.x = 0.5f * (mem.x + xv[t].x);
        sx = (mem.x > 0.5f) ? 1.0f : 0.0f;
        mem.x = (mem.x > 0.5f) ? 0.0f : mem.x;

        mem.y = 0.5f * (mem.y + xv[t].y);
        sy = (mem.y > 0.5f) ? 1.0f : 0.0f;
        mem.y = (mem.y > 0.5f) ? 0.0f : mem.y;

        mem.z = 0.5f * (mem.z + xv[t].z);
        sz = (mem.z > 0.5f) ? 1.0f : 0.0f;
        mem.z = (mem.z > 0.5f) ? 0.0f : mem.z;

        mem.w = 0.5f * (mem.w + xv[t].w);
        sw = (mem.w > 0.5f) ? 1.0f : 0.0f;
        mem.w = (mem.w > 0.5f) ? 0.0f : mem.w;

        xv[t] = make_float4(sx, sy, sz, sw);
    }

    // Phase 3: all 8 stores back-to-back (one write burst).
#pragma unroll
    for (int t = 0; t < T_STEPS; t++) {
        stg_evict_first(&out[(size_t)t * n4 + i], xv[t]);
    }
}

extern "C" void kernel_launch(void* const* d_in, const int* in_sizes, int n_in,
                              void* d_out, int out_size)
{
    const float* x = (const float*)d_in[0];
    float* out = (float*)d_out;

    int total = in_sizes[0];            // 33,554,432
    int per_t = total / T_STEPS;        // 4,194,304
    int n4 = per_t / 4;                 // 1,048,576 float4 per timestep

    int threads = 256;
    int blocks = (n4 + threads - 1) / threads;   // 4096

    lif_kernel<<<blocks, threads>>>(
        (const float4*)x, (float4*)out, n4);
}

// round 14
// speedup vs baseline: 1.0453x; 1.0198x over previous
#include <cuda_runtime.h>

// LIF neuron forward: T=8 leaky-integrate-fire scan.
// 128 MiB read + 128 MiB write per launch.
//
// FINAL (frozen; unchanged resubmit after infra failure). This workload is
// memory-roofline-bound at ~5.7 TB/s sustained mixed 50/50 R/W on this part
// (~72% of 8 TB/s spec; the remainder is bus-turnaround on interleaved
// read/write streams). Verified across 3 hardware runs of this binary:
// wall 45.1/45.1/46.1 us (noise band +-1 us), kernel 37.5 us, rel_err 0.0.
//
// Falsified levers (each a structurally distinct kernel, all 37.5-38.4 us):
//   - MLP 3 vs 8 (reg-hoisted load batch)      -> neutral
//   - occupancy 42% vs 62%                     -> neutral
//   - store batching (phase-separated bursts)  -> neutral
//   - L2 evict_last pinning, frac 1.0 and 0.65 -> neutral (no cross-replay
//     residency survives in this harness)
//   - 256-bit v8.b32 transactions              -> regression (-2 us wall)
//
// Config: createpolicy frac=0.65 cache_hint loads + st.global.cs stores,
// read burst -> register recurrence -> write burst.

constexpr int T_STEPS = 8;

__device__ __forceinline__ float4 ldg_hint(const float4* p, unsigned long long pol) {
    float4 v;
    asm volatile("ld.global.nc.L2::cache_hint.v4.f32 {%0,%1,%2,%3}, [%4], %5;"
                 : "=f"(v.x), "=f"(v.y), "=f"(v.z), "=f"(v.w)
                 : "l"(p), "l"(pol));
    return v;
}

__device__ __forceinline__ void stg_evict_first(float4* p, float4 v) {
    asm volatile("st.global.cs.v4.f32 [%0], {%1,%2,%3,%4};"
                 :: "l"(p), "f"(v.x), "f"(v.y), "f"(v.z), "f"(v.w)
                 : "memory");
}

__global__ __launch_bounds__(256, 4) void lif_kernel(
    const float4* __restrict__ x,
    float4* __restrict__ out,
    int n4)               // float4 elements per timestep
{
    int i = blockIdx.x * blockDim.x + threadIdx.x;
    if (i >= n4) return;

    unsigned long long pol;
    asm volatile("createpolicy.fractional.L2::evict_last.b64 %0, 0.65;" : "=l"(pol));

    // Phase 1: all 8 strided loads back-to-back (one read burst).
    float4 xv[T_STEPS];
#pragma unroll
    for (int t = 0; t < T_STEPS; t++) {
        xv[t] = ldg_hint(&x[(size_t)t * n4 + i], pol);
    }

    // Phase 2: recurrence entirely in registers; spike overwrites xv[t].
    float4 mem = make_float4(0.f, 0.f, 0.f, 0.f);
#pragma unroll
    for (int t = 0; t < T_STEPS; t++) {
        float sx, sy, sz, sw;

        mem.x = 0.5f * (mem.x + xv[t].x);
        sx = (mem.x > 0.5f) ? 1.0f : 0.0f;
        mem.x = (mem.x > 0.5f) ? 0.0f : mem.x;

        mem.y = 0.5f * (mem.y + xv[t].y);
        sy = (mem.y > 0.5f) ? 1.0f : 0.0f;
        mem.y = (mem.y > 0.5f) ? 0.0f : mem.y;

        mem.z = 0.5f * (mem.z + xv[t].z);
        sz = (mem.z > 0.5f) ? 1.0f : 0.0f;
        mem.z = (mem.z > 0.5f) ? 0.0f : mem.z;

        mem.w = 0.5f * (mem.w + xv[t].w);
        sw = (mem.w > 0.5f) ? 1.0f : 0.0f;
        mem.w = (mem.w > 0.5f) ? 0.0f : mem.w;

        xv[t] = make_float4(sx, sy, sz, sw);
    }

    // Phase 3: all 8 stores back-to-back (one write burst).
#pragma unroll
    for (int t = 0; t < T_STEPS; t++) {
        stg_evict_first(&out[(size_t)t * n4 + i], xv[t]);
    }
}

extern "C" void kernel_launch(void* const* d_in, const int* in_sizes, int n_in,
                              void* d_out, int out_size)
{
    const float* x = (const float*)d_in[0];
    float* out = (float*)d_out;

    int total = in_sizes[0];            // 33,554,432
    int per_t = total / T_STEPS;        // 4,194,304
    int n4 = per_t / 4;                 // 1,048,576 float4 per timestep

    int threads = 256;
    int blocks = (n4 + threads - 1) / threads;   // 4096

    lif_kernel<<<blocks, threads>>>(
        (const float4*)x, (float4*)out, n4);
}